// round 3
// baseline (speedup 1.0000x reference)
#include <cuda_runtime.h>
#include <cstdint>

// Problem constants (fixed by the dataset): N=50000 nodes, E=1250000 edges, D=64.
#define D_FEAT 64
#define NMAX   65536   // scratch degree array (static __device__, no allocs allowed)

__device__ int g_deg[NMAX];
__device__ int g_is64;   // 1 if edge_index is int64, 0 if int32

// ---------------------------------------------------------------------------
// Index decode: flag-dependent, uniform branch (read once per thread).
// ---------------------------------------------------------------------------
__device__ __forceinline__ int load_idx(const void* idx, long long i, int is64) {
    if (is64) return (int)((const long long*)idx)[i];
    return ((const int*)idx)[i];
}

// ---------------------------------------------------------------------------
// Kernel 0: detect index dtype. If the buffer is int32 misread as int64,
// values are >= 2^32 (unless the high word is 0, p ~ 1/50000 per sample).
// Sample 512 entries; all-in-range => int64.
// ---------------------------------------------------------------------------
__global__ void detect_kernel(const void* idx, int E, int N) {
    if (threadIdx.x == 0 && blockIdx.x == 0) {
        const long long* p = (const long long*)idx;
        int ok = 1;
        int step = E / 512 > 0 ? E / 512 : 1;
        for (int i = 0; i < E; i += step) {
            long long v = p[i];
            if (v < 0 || v >= (long long)N) { ok = 0; break; }
        }
        g_is64 = ok;
    }
}

// ---------------------------------------------------------------------------
// Kernel 1: zero the degree histogram
// ---------------------------------------------------------------------------
__global__ void zero_deg_kernel(int n) {
    int i = blockIdx.x * blockDim.x + threadIdx.x;
    if (i < n) g_deg[i] = 0;
}

// ---------------------------------------------------------------------------
// Kernel 2: in-degree histogram over dst  (dst = idx[E .. 2E))
// ---------------------------------------------------------------------------
__global__ void hist_kernel(const void* __restrict__ idx, int E) {
    int e = blockIdx.x * blockDim.x + threadIdx.x;
    if (e < E) {
        int is64 = g_is64;
        int d = load_idx(idx, (long long)E + e, is64);
        if (d >= 0 && d < NMAX) atomicAdd(&g_deg[d], 1);
    }
}

// ---------------------------------------------------------------------------
// Kernel 3: out[n][:] = deg[n] * x[n][:]   (handles the x[dst] term densely,
// and initializes the poisoned output buffer)
// ---------------------------------------------------------------------------
__global__ void init_out_kernel(const float4* __restrict__ x4,
                                float4* __restrict__ out4, int n16) {
    int i = blockIdx.x * blockDim.x + threadIdx.x;
    if (i < n16) {
        int node = i >> 4;                 // 16 float4 per node (D=64)
        float d = (float)g_deg[node];
        float4 v = x4[i];
        out4[i] = make_float4(v.x * d, v.y * d, v.z * d, v.w * d);
    }
}

// ---------------------------------------------------------------------------
// Kernel 4: per-edge scatter of (x[src] + edge_attr) via vector red.v4
// 16 threads per edge, each owns one 16B column chunk.
// ---------------------------------------------------------------------------
__device__ __forceinline__ void red_add_v4(float* p, float4 v) {
    asm volatile("red.global.add.v4.f32 [%0], {%1, %2, %3, %4};"
                 :: "l"(p), "f"(v.x), "f"(v.y), "f"(v.z), "f"(v.w)
                 : "memory");
}

__global__ void edge_kernel(const float* __restrict__ x,
                            const float* __restrict__ ea,
                            const void* __restrict__ idx,
                            float* __restrict__ out, int E, int N) {
    int gid = blockIdx.x * blockDim.x + threadIdx.x;   // E*16 = 20M < 2^31
    int e = gid >> 4;
    if (e >= E) return;
    int c = (gid & 15) << 2;   // float column offset: 0,4,...,60

    int is64 = g_is64;
    int s = load_idx(idx, e, is64);                    // src[e]
    int d = load_idx(idx, (long long)E + e, is64);     // dst[e]
    if ((unsigned)s >= (unsigned)N || (unsigned)d >= (unsigned)N) return;

    // x[src] chunk: L2-resident gather (x = 12.8MB << 126MB L2)
    float4 xs = __ldg(reinterpret_cast<const float4*>(x + (size_t)s * D_FEAT + c));
    // edge_attr chunk: streamed once, evict-first so x/out stay L2-resident
    float4 av = __ldcs(reinterpret_cast<const float4*>(ea + (size_t)e * D_FEAT + c));

    float4 m = make_float4(xs.x + av.x, xs.y + av.y, xs.z + av.z, xs.w + av.w);
    red_add_v4(out + (size_t)d * D_FEAT + c, m);
}

// ---------------------------------------------------------------------------
// Launcher (graph-capturable: kernel launches only, same stream => ordered)
// Input identification is ORDER-PROOF:
//   x          = the input whose element count == out_size
//   edge_index = the smaller of the remaining two (2*E elements)
//   edge_attr  = the larger of the remaining two  (E*64 f32 elements)
// Index dtype (int32 vs int64) is detected on-device.
// ---------------------------------------------------------------------------
extern "C" void kernel_launch(void* const* d_in, const int* in_sizes, int n_in,
                              void* d_out, int out_size) {
    int xi = -1;
    for (int i = 0; i < n_in; ++i) {
        if (in_sizes[i] == out_size) { xi = i; break; }
    }
    int a = -1, b = -1;
    for (int i = 0; i < n_in; ++i) {
        if (i == xi) continue;
        if (a < 0) a = i; else b = i;
    }
    int ii = (in_sizes[a] < in_sizes[b]) ? a : b;   // edge_index (smaller)
    int ei = (ii == a) ? b : a;                     // edge_attr  (larger)

    const float* x   = (const float*)d_in[xi];
    const float* ea  = (const float*)d_in[ei];
    const void*  idx = d_in[ii];
    float* out = (float*)d_out;

    const int N = out_size / D_FEAT;        // 50000
    const int E = in_sizes[ii] / 2;         // 1250000
    const int T = 256;

    detect_kernel<<<1, 32>>>(idx, E, N);
    zero_deg_kernel<<<(N + T - 1) / T, T>>>(N);
    hist_kernel<<<(E + T - 1) / T, T>>>(idx, E);

    int n16 = N * (D_FEAT / 4);             // 800K float4 chunks
    init_out_kernel<<<(n16 + T - 1) / T, T>>>(
        (const float4*)x, (float4*)out, n16);

    long long total = (long long)E * 16;    // 20M threads
    int blocks = (int)((total + T - 1) / T);
    edge_kernel<<<blocks, T>>>(x, ea, idx, out, E, N);
}

// round 4
// speedup vs baseline: 1.0378x; 1.0378x over previous
#include <cuda_runtime.h>
#include <cstdint>

// Problem constants (fixed by the dataset): N=50000 nodes, E=1250000 edges, D=64.
#define D_FEAT 64
#define NMAX   65536   // scratch degree array (static __device__, no allocs allowed)

__device__ int g_deg[NMAX];
__device__ int g_is64;   // 1 if edge_index is int64, 0 if int32

// ---------------------------------------------------------------------------
// Index decode: flag-dependent, uniform branch.
// ---------------------------------------------------------------------------
__device__ __forceinline__ int load_idx(const void* idx, long long i, int is64) {
    if (is64) return (int)((const long long*)idx)[i];
    return ((const int*)idx)[i];
}

// ---------------------------------------------------------------------------
// Kernel 1: zero the degree histogram + PARALLEL dtype detection.
// Detection: 32 lanes each load one int64-interpreted sample; for int32 data
// misread as int64 a sample is in [0,N) only with p ~ 2e-5 (high word must be
// zero). All-32-in-range => int64. One ballot, ~0.5us instead of a serial
// single-thread 512-load loop (~30-80us!).
// ---------------------------------------------------------------------------
__global__ void prep_kernel(const void* __restrict__ idx, int E, int N, int n) {
    int i = blockIdx.x * blockDim.x + threadIdx.x;
    if (i < n) g_deg[i] = 0;
    if (blockIdx.x == 0 && threadIdx.x < 32) {
        int step = E / 32;                 // samples within [0, E) int64 slots
        long long v = ((const long long*)idx)[(long long)threadIdx.x * step];
        bool okv = (v >= 0 && v < (long long)N);
        unsigned m = __ballot_sync(0xFFFFFFFFu, okv);
        if (threadIdx.x == 0) g_is64 = (m == 0xFFFFFFFFu) ? 1 : 0;
    }
}

// ---------------------------------------------------------------------------
// Kernel 2: in-degree histogram over dst  (dst = idx[E .. 2E))
// ---------------------------------------------------------------------------
__global__ void hist_kernel(const void* __restrict__ idx, int E) {
    int e = blockIdx.x * blockDim.x + threadIdx.x;
    if (e < E) {
        int is64 = g_is64;
        int d = load_idx(idx, (long long)E + e, is64);
        if (d >= 0 && d < NMAX) atomicAdd(&g_deg[d], 1);
    }
}

// ---------------------------------------------------------------------------
// Kernel 3: out[n][:] = deg[n] * x[n][:]   (x[dst] term handled densely;
// also initializes the poisoned output buffer)
// ---------------------------------------------------------------------------
__global__ void init_out_kernel(const float4* __restrict__ x4,
                                float4* __restrict__ out4, int n16) {
    int i = blockIdx.x * blockDim.x + threadIdx.x;
    if (i < n16) {
        int node = i >> 4;                 // 16 float4 per node (D=64)
        float d = (float)g_deg[node];
        float4 v = x4[i];
        out4[i] = make_float4(v.x * d, v.y * d, v.z * d, v.w * d);
    }
}

// ---------------------------------------------------------------------------
// Kernel 4: per-edge scatter of (x[src] + edge_attr) via vector red.v4
// 16 threads per edge, each owns one 16B column chunk.
// ---------------------------------------------------------------------------
__device__ __forceinline__ void red_add_v4(float* p, float4 v) {
    asm volatile("red.global.add.v4.f32 [%0], {%1, %2, %3, %4};"
                 :: "l"(p), "f"(v.x), "f"(v.y), "f"(v.z), "f"(v.w)
                 : "memory");
}

__global__ void edge_kernel(const float* __restrict__ x,
                            const float* __restrict__ ea,
                            const void* __restrict__ idx,
                            float* __restrict__ out, int E, int N) {
    int gid = blockIdx.x * blockDim.x + threadIdx.x;   // E*16 = 20M < 2^31
    int e = gid >> 4;
    if (e >= E) return;
    int c = (gid & 15) << 2;   // float column offset: 0,4,...,60

    int is64 = g_is64;
    int s = load_idx(idx, e, is64);                    // src[e] (broadcast)
    int d = load_idx(idx, (long long)E + e, is64);     // dst[e] (broadcast)
    if ((unsigned)s >= (unsigned)N || (unsigned)d >= (unsigned)N) return;

    // x[src] chunk: L2-resident gather (x = 12.8MB << 126MB L2)
    float4 xs = __ldg(reinterpret_cast<const float4*>(x + (size_t)s * D_FEAT + c));
    // edge_attr chunk: streamed once, evict-first so x/out stay L2-resident
    float4 av = __ldcs(reinterpret_cast<const float4*>(ea + (size_t)e * D_FEAT + c));

    float4 m = make_float4(xs.x + av.x, xs.y + av.y, xs.z + av.z, xs.w + av.w);
    red_add_v4(out + (size_t)d * D_FEAT + c, m);
}

// ---------------------------------------------------------------------------
// Launcher (graph-capturable: kernel launches only, same stream => ordered)
// Input identification is ORDER-PROOF:
//   x          = the input whose element count == out_size
//   edge_index = the smaller of the remaining two (2*E elements)
//   edge_attr  = the larger of the remaining two  (E*64 f32 elements)
// Index dtype (int32 vs int64) is detected on-device.
// ---------------------------------------------------------------------------
extern "C" void kernel_launch(void* const* d_in, const int* in_sizes, int n_in,
                              void* d_out, int out_size) {
    int xi = -1;
    for (int i = 0; i < n_in; ++i) {
        if (in_sizes[i] == out_size) { xi = i; break; }
    }
    int a = -1, b = -1;
    for (int i = 0; i < n_in; ++i) {
        if (i == xi) continue;
        if (a < 0) a = i; else b = i;
    }
    int ii = (in_sizes[a] < in_sizes[b]) ? a : b;   // edge_index (smaller)
    int ei = (ii == a) ? b : a;                     // edge_attr  (larger)

    const float* x   = (const float*)d_in[xi];
    const float* ea  = (const float*)d_in[ei];
    const void*  idx = d_in[ii];
    float* out = (float*)d_out;

    const int N = out_size / D_FEAT;        // 50000
    const int E = in_sizes[ii] / 2;         // 1250000
    const int T = 256;

    prep_kernel<<<(N + T - 1) / T, T>>>(idx, E, N, N);
    hist_kernel<<<(E + T - 1) / T, T>>>(idx, E);

    int n16 = N * (D_FEAT / 4);             // 800K float4 chunks
    init_out_kernel<<<(n16 + T - 1) / T, T>>>(
        (const float4*)x, (float4*)out, n16);

    long long total = (long long)E * 16;    // 20M threads
    int blocks = (int)((total + T - 1) / T);
    edge_kernel<<<blocks, T>>>(x, ea, idx, out, E, N);
}